// round 5
// baseline (speedup 1.0000x reference)
#include <cuda_runtime.h>

#define EPSV 1e-5f
#define RSQRT8 0.35355339059327373f

// scratch (allocation-free rule: device globals)
__device__ float g_q[4*512*64];
__device__ float g_k[4*512*64];
__device__ float g_v[4*512*64];

typedef unsigned long long ull;

__device__ __forceinline__ ull splat2(float x){
    ull r; unsigned u = __float_as_uint(x);
    asm("mov.b64 %0, {%1,%1};" : "=l"(r) : "r"(u));
    return r;
}
__device__ __forceinline__ ull pack2(float lo, float hi){
    ull r;
    asm("mov.b64 %0, {%1,%2};" : "=l"(r) : "r"(__float_as_uint(lo)), "r"(__float_as_uint(hi)));
    return r;
}
__device__ __forceinline__ void fma2a(ull& d, ull a, ull b){
    asm("fma.rn.f32x2 %0, %1, %2, %0;" : "+l"(d) : "l"(a), "l"(b));
}
__device__ __forceinline__ ull mul2(ull a, ull b){
    ull d; asm("mul.rn.f32x2 %0, %1, %2;" : "=l"(d) : "l"(a), "l"(b));
    return d;
}
__device__ __forceinline__ void add2a(ull& d, ull a){
    asm("add.rn.f32x2 %0, %0, %1;" : "+l"(d) : "l"(a));
}
__device__ __forceinline__ float2 unpack2(ull v){
    unsigned lo, hi;
    asm("mov.b64 {%0,%1}, %2;" : "=r"(lo), "=r"(hi) : "l"(v));
    return make_float2(__uint_as_float(lo), __uint_as_float(hi));
}
__device__ __forceinline__ float hsum2(ull v){
    float2 u = unpack2(v); return u.x + u.y;
}
__device__ __forceinline__ void cpa16(void* sd, const void* g){
    unsigned s = (unsigned)__cvta_generic_to_shared(sd);
    asm volatile("cp.async.cg.shared.global [%0], [%1], 16;" :: "r"(s), "l"(g));
}

// ===================== Kernel 1: LN1 + QKV projection =====================
__global__ void qkv_kernel(const float* __restrict__ h, const float* __restrict__ Wh,
                           const float* __restrict__ g1, const float* __restrict__ b1)
{
    __shared__ float hn[64];
    __shared__ float part[4];
    int row = blockIdx.x, t = threadIdx.x;
    float x = h[row*64 + t];
    float s = x, q = x*x;
    #pragma unroll
    for (int o = 16; o >= 1; o >>= 1){
        s += __shfl_xor_sync(0xffffffffu, s, o);
        q += __shfl_xor_sync(0xffffffffu, q, o);
    }
    if ((t & 31) == 0){ part[t>>5] = s; part[2 + (t>>5)] = q; }
    __syncthreads();
    float mean = (part[0] + part[1]) * (1.f/64.f);
    float var  = (part[2] + part[3]) * (1.f/64.f) - mean*mean;
    float hv = (x - mean) * rsqrtf(var + EPSV) * g1[t] + b1[t];
    hn[t] = hv;
    __syncthreads();
    float aq = 0.f, ak = 0.f, av = 0.f;
    #pragma unroll 8
    for (int i = 0; i < 64; i++){
        float z = hn[i];
        aq = fmaf(z, Wh[i*192 + t],       aq);
        ak = fmaf(z, Wh[i*192 + 64 + t],  ak);
        av = fmaf(z, Wh[i*192 + 128 + t], av);
    }
    g_q[row*64 + t] = aq;
    g_k[row*64 + t] = ak;
    g_v[row*64 + t] = av;
}

// ===================== Kernel 2: fused edge-GEMM + attention + LN2 + MLP =====================
// 512 threads = 16 warps, 8 q-rows/block. Warp w: q-pair pr=w>>2 (rows 2pr,2pr+1),
// head-group hg2=w&3 (heads 2*hg2, 2*hg2+1). lane = k within 32-wide k-tile.
// ew GEMM uses i-pair packing: e pairs {e_i,e_i+1} (natural LDS.128 halves) against
// pre-interleaved weight pairs wre[ip][j] = {W_e[2ip][j], W_e[2ip+1][j]} -> zero splats.
// smem (floats): e_s 2x(256x68)=34816, k_s 4352, v_s 4352, we_raw 1024, wre 1024,
//   q_s 512, y_s 512, z_s 512, hid_s 2048 -> 49152 fl = 196608 B (1 blk/SM, 16 warps)
__global__ void __launch_bounds__(512, 1)
attn_kernel(const float* __restrict__ e, const float* __restrict__ We,
            const float* __restrict__ hin, const float* __restrict__ w1,
            const float* __restrict__ w2, const float* __restrict__ g2,
            const float* __restrict__ b2, float* __restrict__ out)
{
    extern __shared__ float smem[];
    float* e_s    = smem;
    float* k_s    = smem + 34816;
    float* v_s    = smem + 39168;
    float* we_raw = smem + 43520;
    float* wre    = smem + 44544;
    float* q_s    = smem + 45568;
    float* y_s    = smem + 46080;
    float* z_s    = smem + 46592;
    float* hid_s  = smem + 47104;

    const int t    = threadIdx.x;
    const int w    = t >> 5;
    const int lane = t & 31;
    const int pr   = w >> 2;            // q-pair (rows 2pr, 2pr+1)
    const int hg2  = w & 3;             // heads 2*hg2, 2*hg2+1
    const int r0   = pr << 1;
    const int bx   = blockIdx.x;
    const int b    = bx >> 6;           // 64 blocks per batch
    const int q0   = (bx & 63) << 3;    // 8 q rows per block

    const float* eg = e + ((size_t)(b*512 + q0)) * 512 * 64;
    const float* kg = g_k + (size_t)(b*512) * 64;
    const float* vg = g_v + (size_t)(b*512) * 64;
    const float* qg = g_q + (size_t)(b*512 + q0) * 64;

    // ---- group A: W_e + q rows ----
    if (t < 256) cpa16(we_raw + t*4, We + t*4);
    if (t < 128) cpa16(q_s + t*4, qg + t*4);
    asm volatile("cp.async.commit_group;");

    // ---- group B: tile 0 (e, k, v) into buffer 0 ----
    {
        #pragma unroll
        for (int it = 0; it < 8; it++){
            int f = t + it*512; int row = f >> 4, c = f & 15;
            int qq = row >> 5, kk = row & 31;
            cpa16(e_s + row*68 + c*4, eg + (size_t)qq*32768 + (size_t)kk*64 + c*4);
        }
        {
            int row = t >> 4, c = t & 15;
            if (t < 512){
                cpa16(k_s + row*68 + c*4, kg + (size_t)row*64 + c*4);
                cpa16(v_s + row*68 + c*4, vg + (size_t)row*64 + c*4);
            }
        }
        asm volatile("cp.async.commit_group;");
    }

    // ---- wait group A, build interleaved weights wre[ip*16+j] = {We[2ip][j], We[2ip+1][j]} ----
    asm volatile("cp.async.wait_group 1;");
    __syncthreads();
    {
        int ip = t >> 4, j = t & 15;
        ((ull*)wre)[t] = pack2(we_raw[(2*ip)*16 + j], we_raw[(2*ip+1)*16 + j]);
    }
    // (visibility of wre + q_s to all warps is covered by the first in-loop __syncthreads)

    float l[4];          // [row(2)][head(2)]
    ull acc[16];         // [row(2)][head(2)][d2(4)]
    #pragma unroll
    for (int i = 0; i < 4; i++) l[i] = 0.f;
    #pragma unroll
    for (int i = 0; i < 16; i++) acc[i] = 0ull;

    const ulonglong2* wv  = (const ulonglong2*)wre;
    const ulonglong2* q0v = (const ulonglong2*)(q_s + r0*64);
    const ulonglong2* q1v = (const ulonglong2*)(q_s + (r0+1)*64);

    for (int tile = 0; tile < 16; tile++){
        const int buf = tile & 1;
        if (tile < 15){
            const int nb = (tile + 1) & 1;
            const int k0 = (tile + 1) * 32;
            float* ed = e_s + nb*17408;
            float* kd = k_s + nb*2176;
            float* vd = v_s + nb*2176;
            #pragma unroll
            for (int it = 0; it < 8; it++){
                int f = t + it*512; int row = f >> 4, c = f & 15;
                int qq = row >> 5, kk = row & 31;
                cpa16(ed + row*68 + c*4, eg + (size_t)qq*32768 + (size_t)(k0+kk)*64 + c*4);
            }
            {
                int row = t >> 4, c = t & 15;
                cpa16(kd + row*68 + c*4, kg + (size_t)(k0+row)*64 + c*4);
                cpa16(vd + row*68 + c*4, vg + (size_t)(k0+row)*64 + c*4);
            }
            asm volatile("cp.async.commit_group;");
            asm volatile("cp.async.wait_group 1;");
        } else {
            asm volatile("cp.async.wait_group 0;");
        }
        __syncthreads();

        // ---- ew for 2 rows x {e1,e2} x 2 heads, i-pair packed (no splats) ----
        const ulonglong2* er0 = (const ulonglong2*)(e_s + buf*17408 + (r0*32 + lane)*68);
        const ulonglong2* er1 = er0 + 544;   // +32 rows * 68 floats = 544 ull2
        ull a1x_r0=0, a1y_r0=0, a2x_r0=0, a2y_r0=0;   // e1 h0/h1, e2 h0/h1 (row0)
        ull a1x_r1=0, a1y_r1=0, a2x_r1=0, a2y_r1=0;
        #pragma unroll
        for (int i4 = 0; i4 < 16; i4++){
            ulonglong2 d0 = er0[i4];                 // row0 pairs: {2*i4*2..}, halves = ipair 2i4, 2i4+1
            ulonglong2 d1 = er1[i4];
            ulonglong2 wa1 = wv[(2*i4)*8 + hg2];     // ipair 2i4, e1 pair (heads 2hg2,2hg2+1)
            ulonglong2 wa2 = wv[(2*i4)*8 + 4 + hg2]; // ipair 2i4, e2 pair
            ulonglong2 wb1 = wv[(2*i4+1)*8 + hg2];
            ulonglong2 wb2 = wv[(2*i4+1)*8 + 4 + hg2];
            fma2a(a1x_r0, d0.x, wa1.x); fma2a(a1y_r0, d0.x, wa1.y);
            fma2a(a2x_r0, d0.x, wa2.x); fma2a(a2y_r0, d0.x, wa2.y);
            fma2a(a1x_r0, d0.y, wb1.x); fma2a(a1y_r0, d0.y, wb1.y);
            fma2a(a2x_r0, d0.y, wb2.x); fma2a(a2y_r0, d0.y, wb2.y);
            fma2a(a1x_r1, d1.x, wa1.x); fma2a(a1y_r1, d1.x, wa1.y);
            fma2a(a2x_r1, d1.x, wa2.x); fma2a(a2y_r1, d1.x, wa2.y);
            fma2a(a1x_r1, d1.y, wb1.x); fma2a(a1y_r1, d1.y, wb1.y);
            fma2a(a2x_r1, d1.y, wb2.x); fma2a(a2y_r1, d1.y, wb2.y);
        }
        float e1a[4], e2a[4];   // [row*2 + headIdx]
        e1a[0] = hsum2(a1x_r0); e1a[1] = hsum2(a1y_r0);
        e2a[0] = hsum2(a2x_r0); e2a[1] = hsum2(a2y_r0);
        e1a[2] = hsum2(a1x_r1); e1a[3] = hsum2(a1y_r1);
        e2a[2] = hsum2(a2x_r1); e2a[3] = hsum2(a2y_r1);

        // ---- attention for 2 heads x 2 rows ----
        const ulonglong2* kr = (const ulonglong2*)(k_s + buf*2176 + lane*68);
        const ulonglong2* vr = (const ulonglong2*)(v_s + buf*2176 + lane*68);
        #pragma unroll
        for (int hh = 0; hh < 2; hh++){
            const int H = 2*hg2 + hh;
            ulonglong2 ka = kr[2*H], kb = kr[2*H+1];
            ulonglong2 va = vr[2*H], vb = vr[2*H+1];
            ulonglong2 qa0 = q0v[2*H], qb0 = q0v[2*H+1];
            ulonglong2 qa1 = q1v[2*H], qb1 = q1v[2*H+1];
            // row 0
            {
                ull s2 = mul2(qa0.x, ka.x);
                fma2a(s2, qa0.y, ka.y);
                fma2a(s2, qb0.x, kb.x);
                fma2a(s2, qb0.y, kb.y);
                float s = fmaf(hsum2(s2), RSQRT8, e1a[hh]);
                float p = __expf(s);
                l[hh] += p;
                ull gg = splat2(p * e2a[hh]);
                fma2a(acc[4*hh+0], gg, va.x);
                fma2a(acc[4*hh+1], gg, va.y);
                fma2a(acc[4*hh+2], gg, vb.x);
                fma2a(acc[4*hh+3], gg, vb.y);
            }
            // row 1
            {
                ull s2 = mul2(qa1.x, ka.x);
                fma2a(s2, qa1.y, ka.y);
                fma2a(s2, qb1.x, kb.x);
                fma2a(s2, qb1.y, kb.y);
                float s = fmaf(hsum2(s2), RSQRT8, e1a[2+hh]);
                float p = __expf(s);
                l[2+hh] += p;
                ull gg = splat2(p * e2a[2+hh]);
                fma2a(acc[8+4*hh+0], gg, va.x);
                fma2a(acc[8+4*hh+1], gg, va.y);
                fma2a(acc[8+4*hh+2], gg, vb.x);
                fma2a(acc[8+4*hh+3], gg, vb.y);
            }
        }
        __syncthreads();
    }

    // ---- cross-lane butterfly sum of (l, acc) ----
    #pragma unroll
    for (int off = 16; off >= 1; off >>= 1){
        #pragma unroll
        for (int i = 0; i < 4; i++)
            l[i] += __shfl_xor_sync(0xffffffffu, l[i], off);
        #pragma unroll
        for (int i = 0; i < 16; i++)
            add2a(acc[i], __shfl_xor_sync(0xffffffffu, acc[i], off));
    }

    if (lane == 0){
        #pragma unroll
        for (int r = 0; r < 2; r++){
            #pragma unroll
            for (int hh = 0; hh < 2; hh++){
                const int H = 2*hg2 + hh;
                float inv = __fdividef(1.f, l[r*2 + hh]);
                #pragma unroll
                for (int d2 = 0; d2 < 4; d2++){
                    float2 u = unpack2(acc[r*8 + 4*hh + d2]);
                    y_s[(r0 + r)*64 + H*8 + d2*2]     = u.x * inv;
                    y_s[(r0 + r)*64 + H*8 + d2*2 + 1] = u.y * inv;
                }
            }
        }
    }
    __syncthreads();

    // ---- LN2 over (y + h_in): warps 0..7 -> rows 0..7 ----
    if (w < 8){
        const float* hrow = hin + (size_t)(b*512 + q0 + w) * 64;
        float x0 = y_s[w*64 + lane]      + hrow[lane];
        float x1 = y_s[w*64 + lane + 32] + hrow[lane + 32];
        float s = x0 + x1, sq = x0*x0 + x1*x1;
        #pragma unroll
        for (int o = 16; o >= 1; o >>= 1){
            s  += __shfl_xor_sync(0xffffffffu, s, o);
            sq += __shfl_xor_sync(0xffffffffu, sq, o);
        }
        float mean = s * (1.f/64.f);
        float var  = sq * (1.f/64.f) - mean*mean;
        float rs = rsqrtf(var + EPSV);
        z_s[w*64 + lane]      = (x0 - mean) * rs * g2[lane]      + b2[lane];
        z_s[w*64 + lane + 32] = (x1 - mean) * rs * g2[lane + 32] + b2[lane + 32];
    }
    __syncthreads();

    // ---- hidden = relu(z @ w1)  [8 x 256]: thread -> col (t&255), rows 4*(t>>8)..+3 ----
    {
        int col = t & 255, rq = t >> 8;
        float a0 = 0.f, a1 = 0.f, a2 = 0.f, a3 = 0.f;
        const float* zb = z_s + rq*256;     // rows 4rq..4rq+3 = floats rq*256..
        #pragma unroll 8
        for (int i = 0; i < 64; i++){
            float wvv = w1[i*256 + col];
            a0 = fmaf(zb[i],       wvv, a0);
            a1 = fmaf(zb[64 + i],  wvv, a1);
            a2 = fmaf(zb[128 + i], wvv, a2);
            a3 = fmaf(zb[192 + i], wvv, a3);
        }
        float* hb = hid_s + rq*1024;
        hb[col]       = fmaxf(a0, 0.f);
        hb[256 + col] = fmaxf(a1, 0.f);
        hb[512 + col] = fmaxf(a2, 0.f);
        hb[768 + col] = fmaxf(a3, 0.f);
    }
    __syncthreads();

    // ---- out = hidden @ w2 + y : one output element per thread ----
    {
        int d = t & 63, r = t >> 6;
        float a = 0.f;
        #pragma unroll 8
        for (int j = 0; j < 256; j++)
            a = fmaf(hid_s[r*256 + j], w2[j*64 + d], a);
        out[((size_t)(b*512 + q0 + r)) * 64 + d] = a + y_s[r*64 + d];
    }
}

extern "C" void kernel_launch(void* const* d_in, const int* in_sizes, int n_in,
                              void* d_out, int out_size)
{
    const float* h  = (const float*)d_in[0];
    const float* e  = (const float*)d_in[1];
    const float* Wh = (const float*)d_in[2];
    const float* We = (const float*)d_in[3];
    const float* w1 = (const float*)d_in[4];
    const float* w2 = (const float*)d_in[5];
    const float* g1 = (const float*)d_in[6];
    const float* b1 = (const float*)d_in[7];
    const float* g2 = (const float*)d_in[8];
    const float* b2 = (const float*)d_in[9];
    float* out = (float*)d_out;

    cudaFuncSetAttribute(attn_kernel, cudaFuncAttributeMaxDynamicSharedMemorySize, 196608);

    qkv_kernel<<<2048, 64>>>(h, Wh, g1, b1);
    attn_kernel<<<256, 512, 196608>>>(e, We, h, w1, w2, g2, b2, out);
}

// round 6
// speedup vs baseline: 1.3602x; 1.3602x over previous
#include <cuda_runtime.h>

#define EPSV 1e-5f
#define RSQRT8 0.35355339059327373f

// scratch (allocation-free rule: device globals)
__device__ float g_q[4*512*64];
__device__ float g_k[4*512*64];
__device__ float g_v[4*512*64];

typedef unsigned long long ull;

__device__ __forceinline__ ull splat2(float x){
    ull r; unsigned u = __float_as_uint(x);
    asm("mov.b64 %0, {%1,%1};" : "=l"(r) : "r"(u));
    return r;
}
__device__ __forceinline__ void fma2a(ull& d, ull a, ull b){
    asm("fma.rn.f32x2 %0, %1, %2, %0;" : "+l"(d) : "l"(a), "l"(b));
}
__device__ __forceinline__ ull mul2(ull a, ull b){
    ull d; asm("mul.rn.f32x2 %0, %1, %2;" : "=l"(d) : "l"(a), "l"(b));
    return d;
}
__device__ __forceinline__ void add2a(ull& d, ull a){
    asm("add.rn.f32x2 %0, %0, %1;" : "+l"(d) : "l"(a));
}
__device__ __forceinline__ float2 unpack2(ull v){
    unsigned lo, hi;
    asm("mov.b64 {%0,%1}, %2;" : "=r"(lo), "=r"(hi) : "l"(v));
    return make_float2(__uint_as_float(lo), __uint_as_float(hi));
}
__device__ __forceinline__ float hsum2(ull v){
    float2 u = unpack2(v); return u.x + u.y;
}
__device__ __forceinline__ void cpa16(void* sd, const void* g){
    unsigned s = (unsigned)__cvta_generic_to_shared(sd);
    asm volatile("cp.async.cg.shared.global [%0], [%1], 16;" :: "r"(s), "l"(g));
}
__device__ __forceinline__ unsigned tf32r(float x){
    unsigned r; asm("cvt.rna.tf32.f32 %0, %1;" : "=r"(r) : "f"(x)); return r;
}
__device__ __forceinline__ void mma8(float* d, unsigned a0, unsigned a1, unsigned a2, unsigned a3,
                                     unsigned b0, unsigned b1){
    asm("mma.sync.aligned.m16n8k8.row.col.f32.tf32.tf32.f32 "
        "{%0,%1,%2,%3},{%4,%5,%6,%7},{%8,%9},{%0,%1,%2,%3};"
        : "+f"(d[0]), "+f"(d[1]), "+f"(d[2]), "+f"(d[3])
        : "r"(a0), "r"(a1), "r"(a2), "r"(a3), "r"(b0), "r"(b1));
}

// ===================== Kernel 1: LN1 + QKV projection =====================
__global__ void qkv_kernel(const float* __restrict__ h, const float* __restrict__ Wh,
                           const float* __restrict__ g1, const float* __restrict__ b1)
{
    __shared__ float hn[64];
    __shared__ float part[4];
    int row = blockIdx.x, t = threadIdx.x;
    float x = h[row*64 + t];
    float s = x, q = x*x;
    #pragma unroll
    for (int o = 16; o >= 1; o >>= 1){
        s += __shfl_xor_sync(0xffffffffu, s, o);
        q += __shfl_xor_sync(0xffffffffu, q, o);
    }
    if ((t & 31) == 0){ part[t>>5] = s; part[2 + (t>>5)] = q; }
    __syncthreads();
    float mean = (part[0] + part[1]) * (1.f/64.f);
    float var  = (part[2] + part[3]) * (1.f/64.f) - mean*mean;
    float hv = (x - mean) * rsqrtf(var + EPSV) * g1[t] + b1[t];
    hn[t] = hv;
    __syncthreads();
    float aq = 0.f, ak = 0.f, av = 0.f;
    #pragma unroll 8
    for (int i = 0; i < 64; i++){
        float z = hn[i];
        aq = fmaf(z, Wh[i*192 + t],       aq);
        ak = fmaf(z, Wh[i*192 + 64 + t],  ak);
        av = fmaf(z, Wh[i*192 + 128 + t], av);
    }
    g_q[row*64 + t] = aq;
    g_k[row*64 + t] = ak;
    g_v[row*64 + t] = av;
}

// ===================== Kernel 2: fused edge-GEMM(mma.tf32) + attention + LN2 + MLP =====================
// 512 threads = 16 warps, 8 q-rows/block, k-tile = 32.
// Phase 1 (per tile): ew = E_tile[256x64] @ W_e[64x16] via mma.sync.m16n8k8.tf32.
//   Warp w owns M-rows 16w..16w+15 (m = qrow*32 + k). B-frags (all of W_e) persistent in regs.
//   Results -> ew_s[256][18] (cols 0..7 = e1 per head, 8..15 = e2 per head).
// Phase 2 (per tile): attention. Warp w: q-pair pr=w>>2 (rows 2pr,2pr+1), heads 2*(w&3)..+1.
// smem(floats): e_s 2x(256x68)=34816 | k_s 4352 | v_s 4352 | we_raw 1024 | q_s 512 |
//   y_s 512 | z_s 512 | hid_s 2048 | ew_s 4608  -> 52736 fl = 210944 B (1 blk/SM)
__global__ void __launch_bounds__(512, 1)
attn_kernel(const float* __restrict__ e, const float* __restrict__ We,
            const float* __restrict__ hin, const float* __restrict__ w1,
            const float* __restrict__ w2, const float* __restrict__ g2,
            const float* __restrict__ b2, float* __restrict__ out)
{
    extern __shared__ float smem[];
    float* e_s    = smem;
    float* k_s    = smem + 34816;
    float* v_s    = smem + 39168;
    float* we_raw = smem + 43520;
    float* q_s    = smem + 44544;
    float* y_s    = smem + 45056;
    float* z_s    = smem + 45568;
    float* hid_s  = smem + 46080;
    float* ew_s   = smem + 48128;

    const int t    = threadIdx.x;
    const int w    = t >> 5;
    const int lane = t & 31;
    const int pr   = w >> 2;            // attention q-pair (rows 2pr, 2pr+1)
    const int hg2  = w & 3;             // heads 2*hg2, 2*hg2+1
    const int r0   = pr << 1;
    const int bx   = blockIdx.x;
    const int b    = bx >> 6;           // 64 blocks per batch
    const int q0   = (bx & 63) << 3;    // 8 q rows per block

    const float* eg = e + ((size_t)(b*512 + q0)) * 512 * 64;
    const float* kg = g_k + (size_t)(b*512) * 64;
    const float* vg = g_v + (size_t)(b*512) * 64;
    const float* qg = g_q + (size_t)(b*512 + q0) * 64;

    // ---- group A: W_e + q rows ----
    if (t < 256) cpa16(we_raw + t*4, We + t*4);
    if (t < 128) cpa16(q_s + t*4, qg + t*4);
    asm volatile("cp.async.commit_group;");

    // ---- group B: tile 0 (e, k, v) into buffer 0 ----
    {
        #pragma unroll
        for (int it = 0; it < 8; it++){
            int f = t + it*512; int row = f >> 4, c = f & 15;
            int qq = row >> 5, kk = row & 31;
            cpa16(e_s + row*68 + c*4, eg + (size_t)qq*32768 + (size_t)kk*64 + c*4);
        }
        {
            int row = t >> 4, c = t & 15;
            cpa16(k_s + row*68 + c*4, kg + (size_t)row*64 + c*4);
            cpa16(v_s + row*68 + c*4, vg + (size_t)row*64 + c*4);
        }
        asm volatile("cp.async.commit_group;");
    }

    // ---- wait group A; build persistent B fragments (tf32, rna-rounded) ----
    asm volatile("cp.async.wait_group 1;");
    __syncthreads();
    unsigned b0f[16], b1f[16];
    {
        const int kq = lane & 3, nq = lane >> 2;
        #pragma unroll
        for (int s = 0; s < 8; s++){
            #pragma unroll
            for (int n = 0; n < 2; n++){
                b0f[s*2+n] = tf32r(we_raw[(s*8 + kq)*16     + n*8 + nq]);
                b1f[s*2+n] = tf32r(we_raw[(s*8 + kq + 4)*16 + n*8 + nq]);
            }
        }
    }

    float l[4];          // [row(2)][head(2)]
    ull acc[16];         // [row(2)][head(2)][d2(4)]
    #pragma unroll
    for (int i = 0; i < 4; i++) l[i] = 0.f;
    #pragma unroll
    for (int i = 0; i < 16; i++) acc[i] = 0ull;

    const ulonglong2* q0v = (const ulonglong2*)(q_s + r0*64);
    const ulonglong2* q1v = (const ulonglong2*)(q_s + (r0+1)*64);

    for (int tile = 0; tile < 16; tile++){
        const int buf = tile & 1;
        if (tile < 15){
            const int nb = (tile + 1) & 1;
            const int k0 = (tile + 1) * 32;
            float* ed = e_s + nb*17408;
            float* kd = k_s + nb*2176;
            float* vd = v_s + nb*2176;
            #pragma unroll
            for (int it = 0; it < 8; it++){
                int f = t + it*512; int row = f >> 4, c = f & 15;
                int qq = row >> 5, kk = row & 31;
                cpa16(ed + row*68 + c*4, eg + (size_t)qq*32768 + (size_t)(k0+kk)*64 + c*4);
            }
            {
                int row = t >> 4, c = t & 15;
                cpa16(kd + row*68 + c*4, kg + (size_t)(k0+row)*64 + c*4);
                cpa16(vd + row*68 + c*4, vg + (size_t)(k0+row)*64 + c*4);
            }
            asm volatile("cp.async.commit_group;");
            asm volatile("cp.async.wait_group 1;");
        } else {
            asm volatile("cp.async.wait_group 0;");
        }
        __syncthreads();   // tile data ready; previous tile's ew_s reads done

        // ---- Phase 1: ew via tensor cores. Warp w -> M rows 16w..16w+15 ----
        {
            const float* eA = e_s + buf*17408 + (w*16 + (lane>>2))*68 + (lane&3);
            float d0[4] = {0.f,0.f,0.f,0.f};
            float d1[4] = {0.f,0.f,0.f,0.f};
            #pragma unroll
            for (int s = 0; s < 8; s++){
                unsigned a0 = tf32r(eA[s*8]);
                unsigned a2 = tf32r(eA[s*8 + 4]);
                unsigned a1 = tf32r(eA[544 + s*8]);
                unsigned a3 = tf32r(eA[544 + s*8 + 4]);
                mma8(d0, a0, a1, a2, a3, b0f[s*2],   b1f[s*2]);
                mma8(d1, a0, a1, a2, a3, b0f[s*2+1], b1f[s*2+1]);
            }
            float* ewp = ew_s + (w*16 + (lane>>2))*18 + 2*(lane&3);
            *(float2*)(ewp)           = make_float2(d0[0], d0[1]);
            *(float2*)(ewp + 8)       = make_float2(d1[0], d1[1]);
            *(float2*)(ewp + 144)     = make_float2(d0[2], d0[3]);
            *(float2*)(ewp + 144 + 8) = make_float2(d1[2], d1[3]);
        }
        __syncthreads();   // ew_s ready

        // ---- Phase 2: attention for 2 heads x 2 rows ----
        const float* ewr0 = ew_s + (r0*32 + lane)*18 + 2*hg2;
        const float* ewr1 = ewr0 + 576;   // +32 rows * 18
        float2 e1p0 = *(const float2*)(ewr0);
        float2 e2p0 = *(const float2*)(ewr0 + 8);
        float2 e1p1 = *(const float2*)(ewr1);
        float2 e2p1 = *(const float2*)(ewr1 + 8);
        float e1a[4] = {e1p0.x, e1p0.y, e1p1.x, e1p1.y};   // [row*2 + headIdx]
        float e2a[4] = {e2p0.x, e2p0.y, e2p1.x, e2p1.y};

        const ulonglong2* kr = (const ulonglong2*)(k_s + buf*2176 + lane*68);
        const ulonglong2* vr = (const ulonglong2*)(v_s + buf*2176 + lane*68);
        #pragma unroll
        for (int hh = 0; hh < 2; hh++){
            const int H = 2*hg2 + hh;
            ulonglong2 ka = kr[2*H], kb = kr[2*H+1];
            ulonglong2 va = vr[2*H], vb = vr[2*H+1];
            ulonglong2 qa0 = q0v[2*H], qb0 = q0v[2*H+1];
            ulonglong2 qa1 = q1v[2*H], qb1 = q1v[2*H+1];
            // row 0
            {
                ull s2 = mul2(qa0.x, ka.x);
                fma2a(s2, qa0.y, ka.y);
                fma2a(s2, qb0.x, kb.x);
                fma2a(s2, qb0.y, kb.y);
                float s = fmaf(hsum2(s2), RSQRT8, e1a[hh]);
                float p = __expf(s);
                l[hh] += p;
                ull gg = splat2(p * e2a[hh]);
                fma2a(acc[4*hh+0], gg, va.x);
                fma2a(acc[4*hh+1], gg, va.y);
                fma2a(acc[4*hh+2], gg, vb.x);
                fma2a(acc[4*hh+3], gg, vb.y);
            }
            // row 1
            {
                ull s2 = mul2(qa1.x, ka.x);
                fma2a(s2, qa1.y, ka.y);
                fma2a(s2, qb1.x, kb.x);
                fma2a(s2, qb1.y, kb.y);
                float s = fmaf(hsum2(s2), RSQRT8, e1a[2+hh]);
                float p = __expf(s);
                l[2+hh] += p;
                ull gg = splat2(p * e2a[2+hh]);
                fma2a(acc[8+4*hh+0], gg, va.x);
                fma2a(acc[8+4*hh+1], gg, va.y);
                fma2a(acc[8+4*hh+2], gg, vb.x);
                fma2a(acc[8+4*hh+3], gg, vb.y);
            }
        }
    }

    // ---- cross-lane butterfly sum of (l, acc) ----
    #pragma unroll
    for (int off = 16; off >= 1; off >>= 1){
        #pragma unroll
        for (int i = 0; i < 4; i++)
            l[i] += __shfl_xor_sync(0xffffffffu, l[i], off);
        #pragma unroll
        for (int i = 0; i < 16; i++)
            add2a(acc[i], __shfl_xor_sync(0xffffffffu, acc[i], off));
    }

    if (lane == 0){
        #pragma unroll
        for (int r = 0; r < 2; r++){
            #pragma unroll
            for (int hh = 0; hh < 2; hh++){
                const int H = 2*hg2 + hh;
                float inv = __fdividef(1.f, l[r*2 + hh]);
                #pragma unroll
                for (int d2 = 0; d2 < 4; d2++){
                    float2 u = unpack2(acc[r*8 + 4*hh + d2]);
                    y_s[(r0 + r)*64 + H*8 + d2*2]     = u.x * inv;
                    y_s[(r0 + r)*64 + H*8 + d2*2 + 1] = u.y * inv;
                }
            }
        }
    }
    __syncthreads();

    // ---- LN2 over (y + h_in): warps 0..7 -> rows 0..7 ----
    if (w < 8){
        const float* hrow = hin + (size_t)(b*512 + q0 + w) * 64;
        float x0 = y_s[w*64 + lane]      + hrow[lane];
        float x1 = y_s[w*64 + lane + 32] + hrow[lane + 32];
        float s = x0 + x1, sq = x0*x0 + x1*x1;
        #pragma unroll
        for (int o = 16; o >= 1; o >>= 1){
            s  += __shfl_xor_sync(0xffffffffu, s, o);
            sq += __shfl_xor_sync(0xffffffffu, sq, o);
        }
        float mean = s * (1.f/64.f);
        float var  = sq * (1.f/64.f) - mean*mean;
        float rs = rsqrtf(var + EPSV);
        z_s[w*64 + lane]      = (x0 - mean) * rs * g2[lane]      + b2[lane];
        z_s[w*64 + lane + 32] = (x1 - mean) * rs * g2[lane + 32] + b2[lane + 32];
    }
    __syncthreads();

    // ---- hidden = relu(z @ w1)  [8 x 256]: thread -> col (t&255), rows 4*(t>>8)..+3 ----
    {
        int col = t & 255, rq = t >> 8;
        float a0 = 0.f, a1 = 0.f, a2 = 0.f, a3 = 0.f;
        const float* zb = z_s + rq*256;
        #pragma unroll 8
        for (int i = 0; i < 64; i++){
            float wvv = w1[i*256 + col];
            a0 = fmaf(zb[i],       wvv, a0);
            a1 = fmaf(zb[64 + i],  wvv, a1);
            a2 = fmaf(zb[128 + i], wvv, a2);
            a3 = fmaf(zb[192 + i], wvv, a3);
        }
        float* hb = hid_s + rq*1024;
        hb[col]       = fmaxf(a0, 0.f);
        hb[256 + col] = fmaxf(a1, 0.f);
        hb[512 + col] = fmaxf(a2, 0.f);
        hb[768 + col] = fmaxf(a3, 0.f);
    }
    __syncthreads();

    // ---- out = hidden @ w2 + y : one output element per thread ----
    {
        int d = t & 63, r = t >> 6;
        float a = 0.f;
        #pragma unroll 8
        for (int j = 0; j < 256; j++)
            a = fmaf(hid_s[r*256 + j], w2[j*64 + d], a);
        out[((size_t)(b*512 + q0 + r)) * 64 + d] = a + y_s[r*64 + d];
    }
}

extern "C" void kernel_launch(void* const* d_in, const int* in_sizes, int n_in,
                              void* d_out, int out_size)
{
    const float* h  = (const float*)d_in[0];
    const float* e  = (const float*)d_in[1];
    const float* Wh = (const float*)d_in[2];
    const float* We = (const float*)d_in[3];
    const float* w1 = (const float*)d_in[4];
    const float* w2 = (const float*)d_in[5];
    const float* g1 = (const float*)d_in[6];
    const float* b1 = (const float*)d_in[7];
    const float* g2 = (const float*)d_in[8];
    const float* b2 = (const float*)d_in[9];
    float* out = (float*)d_out;

    cudaFuncSetAttribute(attn_kernel, cudaFuncAttributeMaxDynamicSharedMemorySize, 210944);

    qkv_kernel<<<2048, 64>>>(h, Wh, g1, b1);
    attn_kernel<<<256, 512, 210944>>>(e, We, h, w1, w2, g2, b2, out);
}

// round 7
// speedup vs baseline: 1.5773x; 1.1596x over previous
#include <cuda_runtime.h>

#define EPSV 1e-5f
#define RSQRT8 0.35355339059327373f

// scratch (allocation-free rule: device globals)
__device__ float g_q[4*512*64];
__device__ float g_k[4*512*64];
__device__ float g_v[4*512*64];

typedef unsigned long long ull;

__device__ __forceinline__ ull splat2(float x){
    ull r; unsigned u = __float_as_uint(x);
    asm("mov.b64 %0, {%1,%1};" : "=l"(r) : "r"(u));
    return r;
}
__device__ __forceinline__ void fma2a(ull& d, ull a, ull b){
    asm("fma.rn.f32x2 %0, %1, %2, %0;" : "+l"(d) : "l"(a), "l"(b));
}
__device__ __forceinline__ ull mul2(ull a, ull b){
    ull d; asm("mul.rn.f32x2 %0, %1, %2;" : "=l"(d) : "l"(a), "l"(b));
    return d;
}
__device__ __forceinline__ void add2a(ull& d, ull a){
    asm("add.rn.f32x2 %0, %0, %1;" : "+l"(d) : "l"(a));
}
__device__ __forceinline__ float2 unpack2(ull v){
    unsigned lo, hi;
    asm("mov.b64 {%0,%1}, %2;" : "=r"(lo), "=r"(hi) : "l"(v));
    return make_float2(__uint_as_float(lo), __uint_as_float(hi));
}
__device__ __forceinline__ float hsum2(ull v){
    float2 u = unpack2(v); return u.x + u.y;
}
__device__ __forceinline__ void cpa16(const void* sd, const void* g){
    unsigned s = (unsigned)__cvta_generic_to_shared(sd);
    asm volatile("cp.async.cg.shared.global [%0], [%1], 16;" :: "r"(s), "l"(g));
}
__device__ __forceinline__ unsigned tf32r(float x){
    unsigned r; asm("cvt.rna.tf32.f32 %0, %1;" : "=r"(r) : "f"(x)); return r;
}
__device__ __forceinline__ void mma8(float* d, unsigned a0, unsigned a1, unsigned a2, unsigned a3,
                                     unsigned b0, unsigned b1){
    asm("mma.sync.aligned.m16n8k8.row.col.f32.tf32.tf32.f32 "
        "{%0,%1,%2,%3},{%4,%5,%6,%7},{%8,%9},{%0,%1,%2,%3};"
        : "+f"(d[0]), "+f"(d[1]), "+f"(d[2]), "+f"(d[3])
        : "r"(a0), "r"(a1), "r"(a2), "r"(a3), "r"(b0), "r"(b1));
}

// ===================== Kernel 1: LN1 + QKV projection (4 rows/block) =====================
__global__ void __launch_bounds__(256)
qkv_kernel(const float* __restrict__ h, const float* __restrict__ Wh,
           const float* __restrict__ g1, const float* __restrict__ b1)
{
    __shared__ float hn[4][64];
    __shared__ float part[4][4];
    int t = threadIdx.x;
    int g = t >> 6, tl = t & 63;
    int row = blockIdx.x*4 + g;
    float x = h[row*64 + tl];
    float s = x, q = x*x;
    #pragma unroll
    for (int o = 16; o >= 1; o >>= 1){
        s += __shfl_xor_sync(0xffffffffu, s, o);
        q += __shfl_xor_sync(0xffffffffu, q, o);
    }
    if ((tl & 31) == 0){ part[g][tl>>5] = s; part[g][2 + (tl>>5)] = q; }
    __syncthreads();
    float mean = (part[g][0] + part[g][1]) * (1.f/64.f);
    float var  = (part[g][2] + part[g][3]) * (1.f/64.f) - mean*mean;
    float hv = (x - mean) * rsqrtf(var + EPSV) * g1[tl] + b1[tl];
    hn[g][tl] = hv;
    __syncthreads();
    float aq = 0.f, ak = 0.f, av = 0.f;
    #pragma unroll 8
    for (int i = 0; i < 64; i++){
        float z = hn[g][i];
        aq = fmaf(z, Wh[i*192 + tl],       aq);
        ak = fmaf(z, Wh[i*192 + 64 + tl],  ak);
        av = fmaf(z, Wh[i*192 + 128 + tl], av);
    }
    g_q[row*64 + tl] = aq;
    g_k[row*64 + tl] = ak;
    g_v[row*64 + tl] = av;
}

// ===================== Kernel 2: fused edge-GEMM(mma.tf32) + attention + LN2 + MLP =====================
// 256 threads = 8 warps, 4 q-rows/block, k-tile 32, TWO blocks per SM (112 KB smem each).
// Phase 1: ew = E_tile[128x64] @ W_e[64x16] via mma.m16n8k8.tf32; warp w -> M-rows 16w..16w+15.
// Phase 2: warp w: q-pair pr=w>>2 (rows 2pr,2pr+1), heads 2*(w&3), 2*(w&3)+1.
// smem(floats, total 28672 = 114688 B):
//   e_s   [0, 17408)   2 x (128x68)
//   k_s   [17408,21760) 2 x (32x68)   [y_s(256) overlays 17408.. after loop]
//   v_s   [21760,26112) 2 x (32x68)
//   q_s   [26112,26368)
//   ew_s  [26368,28672) 128x18        [we_raw(1024) before loop; z(256)+hid(1024) after]
__global__ void __launch_bounds__(256, 2)
attn_kernel(const float* __restrict__ e, const float* __restrict__ We,
            const float* __restrict__ hin, const float* __restrict__ w1,
            const float* __restrict__ w2, const float* __restrict__ g2,
            const float* __restrict__ b2, float* __restrict__ out)
{
    extern __shared__ float smem[];
    float* e_s    = smem;
    float* k_s    = smem + 17408;
    float* v_s    = smem + 21760;
    float* q_s    = smem + 26112;
    float* ew_s   = smem + 26368;
    float* we_raw = ew_s;           // overlay (used only before first tile's phase 1)
    float* y_s    = k_s;            // overlay (used only after loop)
    float* z_s    = ew_s;           // overlay (after loop)
    float* hid_s  = ew_s + 256;     // overlay (after loop)

    const int t    = threadIdx.x;
    const int w    = t >> 5;
    const int lane = t & 31;
    const int pr   = w >> 2;            // attention q-pair (rows 2pr, 2pr+1)
    const int hg2  = w & 3;             // heads 2*hg2, 2*hg2+1
    const int r0   = pr << 1;
    const int bx   = blockIdx.x;
    const int b    = bx >> 7;           // 128 blocks per batch
    const int q0   = (bx & 127) << 2;   // 4 q rows per block

    const float* eg = e + ((size_t)(b*512 + q0)) * 512 * 64;
    const float* kg = g_k + (size_t)(b*512) * 64;
    const float* vg = g_v + (size_t)(b*512) * 64;
    const float* qg = g_q + (size_t)(b*512 + q0) * 64;

    // ---- hoisted copy addressing ----
    const int rc = t >> 4;              // 0..15
    const int cc = t & 15;
    // e rows for it=0..7: (it>>1)*32 + rc + 16*(it&1); addr imm = (it>>1)*131072 + (it&1)*4096 B
    const char* peb = (const char*)(eg + (size_t)rc*64 + cc*4);
    const char* pkb = (const char*)(kg + (size_t)rc*64 + cc*4);
    const char* pvb = (const char*)(vg + (size_t)rc*64 + cc*4);
    const int e_dst0 = (rc*68 + cc*4) * 4;  // byte offset of it=0 chunk within buffer

    // ---- group A: W_e + q rows ----
    cpa16((char*)we_raw + t*16, We + t*4);
    if (t < 64) cpa16((char*)q_s + t*16, qg + t*4);
    asm volatile("cp.async.commit_group;");

    // ---- group B: tile 0 (e, k, v) into buffer 0 ----
    {
        const char* esd = (const char*)e_s + e_dst0;
        #pragma unroll
        for (int it = 0; it < 8; it++)
            cpa16(esd + it*4352, peb + (it>>1)*131072 + (it&1)*4096);
        const char* ksd = (const char*)k_s + e_dst0;
        const char* vsd = (const char*)v_s + e_dst0;
        #pragma unroll
        for (int it = 0; it < 2; it++){
            cpa16(ksd + it*4352, pkb + it*4096);
            cpa16(vsd + it*4352, pvb + it*4096);
        }
        asm volatile("cp.async.commit_group;");
    }
    peb += 8192; pkb += 8192; pvb += 8192;   // now point at tile 1

    // ---- wait group A; build persistent B fragments (tf32, rna) ----
    asm volatile("cp.async.wait_group 1;");
    __syncthreads();
    unsigned b0f[16], b1f[16];
    {
        const int kq = lane & 3, nq = lane >> 2;
        #pragma unroll
        for (int s = 0; s < 8; s++){
            #pragma unroll
            for (int n = 0; n < 2; n++){
                b0f[s*2+n] = tf32r(we_raw[(s*8 + kq)*16     + n*8 + nq]);
                b1f[s*2+n] = tf32r(we_raw[(s*8 + kq + 4)*16 + n*8 + nq]);
            }
        }
    }

    float l[4];          // [row(2)][head(2)]
    ull acc[16];         // [row(2)][head(2)][d2(4)]
    #pragma unroll
    for (int i = 0; i < 4; i++) l[i] = 0.f;
    #pragma unroll
    for (int i = 0; i < 16; i++) acc[i] = 0ull;

    const ulonglong2* q0v = (const ulonglong2*)(q_s + r0*64);
    const ulonglong2* q1v = (const ulonglong2*)(q_s + (r0+1)*64);

    for (int tile = 0; tile < 16; tile++){
        const int buf = tile & 1;
        if (tile < 15){
            const int nb = (tile + 1) & 1;
            const char* esd = (const char*)(e_s + nb*8704) + e_dst0;
            #pragma unroll
            for (int it = 0; it < 8; it++)
                cpa16(esd + it*4352, peb + (it>>1)*131072 + (it&1)*4096);
            const char* ksd = (const char*)(k_s + nb*2176) + e_dst0;
            const char* vsd = (const char*)(v_s + nb*2176) + e_dst0;
            #pragma unroll
            for (int it = 0; it < 2; it++){
                cpa16(ksd + it*4352, pkb + it*4096);
                cpa16(vsd + it*4352, pvb + it*4096);
            }
            asm volatile("cp.async.commit_group;");
            asm volatile("cp.async.wait_group 1;");
            peb += 8192; pkb += 8192; pvb += 8192;
        } else {
            asm volatile("cp.async.wait_group 0;");
        }
        __syncthreads();   // tile data ready; previous tile's ew_s reads done

        // ---- Phase 1: ew via tensor cores. Warp w -> M rows 16w..16w+15 ----
        {
            const float* eA = e_s + buf*8704 + (w*16 + (lane>>2))*68 + (lane&3);
            float d0[4] = {0.f,0.f,0.f,0.f};
            float d1[4] = {0.f,0.f,0.f,0.f};
            #pragma unroll
            for (int s = 0; s < 8; s++){
                unsigned a0 = tf32r(eA[s*8]);
                unsigned a2 = tf32r(eA[s*8 + 4]);
                unsigned a1 = tf32r(eA[544 + s*8]);
                unsigned a3 = tf32r(eA[544 + s*8 + 4]);
                mma8(d0, a0, a1, a2, a3, b0f[s*2],   b1f[s*2]);
                mma8(d1, a0, a1, a2, a3, b0f[s*2+1], b1f[s*2+1]);
            }
            float* ewp = ew_s + (w*16 + (lane>>2))*18 + 2*(lane&3);
            *(float2*)(ewp)           = make_float2(d0[0], d0[1]);
            *(float2*)(ewp + 8)       = make_float2(d1[0], d1[1]);
            *(float2*)(ewp + 144)     = make_float2(d0[2], d0[3]);
            *(float2*)(ewp + 144 + 8) = make_float2(d1[2], d1[3]);
        }
        __syncthreads();   // ew_s ready

        // ---- Phase 2: attention for 2 heads x 2 rows ----
        const float* ewr0 = ew_s + (r0*32 + lane)*18 + 2*hg2;
        const float* ewr1 = ewr0 + 576;   // +32 rows * 18
        float2 e1p0 = *(const float2*)(ewr0);
        float2 e2p0 = *(const float2*)(ewr0 + 8);
        float2 e1p1 = *(const float2*)(ewr1);
        float2 e2p1 = *(const float2*)(ewr1 + 8);
        float e1a[4] = {e1p0.x, e1p0.y, e1p1.x, e1p1.y};   // [row*2 + headIdx]
        float e2a[4] = {e2p0.x, e2p0.y, e2p1.x, e2p1.y};

        const ulonglong2* kr = (const ulonglong2*)(k_s + buf*2176 + lane*68);
        const ulonglong2* vr = (const ulonglong2*)(v_s + buf*2176 + lane*68);
        #pragma unroll
        for (int hh = 0; hh < 2; hh++){
            const int H = 2*hg2 + hh;
            ulonglong2 ka = kr[2*H], kb = kr[2*H+1];
            ulonglong2 va = vr[2*H], vb = vr[2*H+1];
            ulonglong2 qa0 = q0v[2*H], qb0 = q0v[2*H+1];
            ulonglong2 qa1 = q1v[2*H], qb1 = q1v[2*H+1];
            // row 0
            {
                ull s2 = mul2(qa0.x, ka.x);
                fma2a(s2, qa0.y, ka.y);
                fma2a(s2, qb0.x, kb.x);
                fma2a(s2, qb0.y, kb.y);
                float s = fmaf(hsum2(s2), RSQRT8, e1a[hh]);
                float p = __expf(s);
                l[hh] += p;
                ull gg = splat2(p * e2a[hh]);
                fma2a(acc[4*hh+0], gg, va.x);
                fma2a(acc[4*hh+1], gg, va.y);
                fma2a(acc[4*hh+2], gg, vb.x);
                fma2a(acc[4*hh+3], gg, vb.y);
            }
            // row 1
            {
                ull s2 = mul2(qa1.x, ka.x);
                fma2a(s2, qa1.y, ka.y);
                fma2a(s2, qb1.x, kb.x);
                fma2a(s2, qb1.y, kb.y);
                float s = fmaf(hsum2(s2), RSQRT8, e1a[2+hh]);
                float p = __expf(s);
                l[2+hh] += p;
                ull gg = splat2(p * e2a[2+hh]);
                fma2a(acc[8+4*hh+0], gg, va.x);
                fma2a(acc[8+4*hh+1], gg, va.y);
                fma2a(acc[8+4*hh+2], gg, vb.x);
                fma2a(acc[8+4*hh+3], gg, vb.y);
            }
        }
    }

    // ---- cross-lane butterfly sum of (l, acc) ----
    #pragma unroll
    for (int off = 16; off >= 1; off >>= 1){
        #pragma unroll
        for (int i = 0; i < 4; i++)
            l[i] += __shfl_xor_sync(0xffffffffu, l[i], off);
        #pragma unroll
        for (int i = 0; i < 16; i++)
            add2a(acc[i], __shfl_xor_sync(0xffffffffu, acc[i], off));
    }

    if (lane == 0){
        #pragma unroll
        for (int r = 0; r < 2; r++){
            #pragma unroll
            for (int hh = 0; hh < 2; hh++){
                const int H = 2*hg2 + hh;
                float inv = __fdividef(1.f, l[r*2 + hh]);
                #pragma unroll
                for (int d2 = 0; d2 < 4; d2++){
                    float2 u = unpack2(acc[r*8 + 4*hh + d2]);
                    y_s[(r0 + r)*64 + H*8 + d2*2]     = u.x * inv;
                    y_s[(r0 + r)*64 + H*8 + d2*2 + 1] = u.y * inv;
                }
            }
        }
    }
    __syncthreads();

    // ---- LN2 over (y + h_in): warps 0..3 -> rows 0..3 ----
    if (w < 4){
        const float* hrow = hin + (size_t)(b*512 + q0 + w) * 64;
        float x0 = y_s[w*64 + lane]      + hrow[lane];
        float x1 = y_s[w*64 + lane + 32] + hrow[lane + 32];
        float s = x0 + x1, sq = x0*x0 + x1*x1;
        #pragma unroll
        for (int o = 16; o >= 1; o >>= 1){
            s  += __shfl_xor_sync(0xffffffffu, s, o);
            sq += __shfl_xor_sync(0xffffffffu, sq, o);
        }
        float mean = s * (1.f/64.f);
        float var  = sq * (1.f/64.f) - mean*mean;
        float rs = rsqrtf(var + EPSV);
        z_s[w*64 + lane]      = (x0 - mean) * rs * g2[lane]      + b2[lane];
        z_s[w*64 + lane + 32] = (x1 - mean) * rs * g2[lane + 32] + b2[lane + 32];
    }
    __syncthreads();

    // ---- hidden = relu(z @ w1)  [4 x 256]: one column per thread ----
    {
        int col = t;
        float a0 = 0.f, a1 = 0.f, a2 = 0.f, a3 = 0.f;
        #pragma unroll 8
        for (int i = 0; i < 64; i++){
            float wvv = w1[i*256 + col];
            a0 = fmaf(z_s[i],       wvv, a0);
            a1 = fmaf(z_s[64 + i],  wvv, a1);
            a2 = fmaf(z_s[128 + i], wvv, a2);
            a3 = fmaf(z_s[192 + i], wvv, a3);
        }
        hid_s[col]       = fmaxf(a0, 0.f);
        hid_s[256 + col] = fmaxf(a1, 0.f);
        hid_s[512 + col] = fmaxf(a2, 0.f);
        hid_s[768 + col] = fmaxf(a3, 0.f);
    }
    __syncthreads();

    // ---- out = hidden @ w2 + y : one output element per thread ----
    {
        int d = t & 63, r = t >> 6;
        float a = 0.f;
        #pragma unroll 8
        for (int j = 0; j < 256; j++)
            a = fmaf(hid_s[r*256 + j], w2[j*64 + d], a);
        out[((size_t)(b*512 + q0 + r)) * 64 + d] = a + y_s[r*64 + d];
    }
}

extern "C" void kernel_launch(void* const* d_in, const int* in_sizes, int n_in,
                              void* d_out, int out_size)
{
    const float* h  = (const float*)d_in[0];
    const float* e  = (const float*)d_in[1];
    const float* Wh = (const float*)d_in[2];
    const float* We = (const float*)d_in[3];
    const float* w1 = (const float*)d_in[4];
    const float* w2 = (const float*)d_in[5];
    const float* g1 = (const float*)d_in[6];
    const float* b1 = (const float*)d_in[7];
    const float* g2 = (const float*)d_in[8];
    const float* b2 = (const float*)d_in[9];
    float* out = (float*)d_out;

    cudaFuncSetAttribute(attn_kernel, cudaFuncAttributeMaxDynamicSharedMemorySize, 114688);

    qkv_kernel<<<512, 256>>>(h, Wh, g1, b1);
    attn_kernel<<<512, 256, 114688>>>(e, We, h, w1, w2, g2, b2, out);
}